// round 1
// baseline (speedup 1.0000x reference)
#include <cuda_runtime.h>
#include <math.h>

#define DTc 1e-4f
#define LN_EPS 1e-5f
#define B_ 16
#define S_ 4096
#define D_ 256
#define N_ 16
#define CHUNK 64
#define NCHUNK (S_/CHUNK)   // 64

// scratch (no cudaMalloc allowed)
__device__ float g_H[B_*S_*N_];          // 4 MB: per-chunk local scans
__device__ float g_carry[B_*NCHUNK*N_];  // 64 KB: global state at each chunk start

// ---------------------------------------------------------------------------
// K1: U = DT * x @ Bm^T per 64-row chunk, then in-block local scan (h0 = 0).
// Thread layout: 512 thr = 32 t x 16 n, two passes cover 64 t.
// ---------------------------------------------------------------------------
__global__ void __launch_bounds__(512,2) k1(const float* __restrict__ x,
                                            const float* __restrict__ A,
                                            const float* __restrict__ Bm){
    extern __shared__ float sm[];
    float* sx = sm;                        // [64][260] padded
    float* sw = sm + 64*260;               // [16][260] padded (DT*Bm)
    float* su = sm + 64*260 + 16*260;      // [64][17]  padded
    const int chunk = blockIdx.x, b = blockIdx.y;
    const int tid = threadIdx.x;

    // stage x tile (64 rows x 256) coalesced, padded rows
    const float4* xg = (const float4*)(x + (size_t)(b*S_ + chunk*CHUNK)*D_);
    for (int i = tid; i < 64*64; i += 512){
        int t = i >> 6, q = i & 63;
        *(float4*)(sx + t*260 + q*4) = xg[t*64 + q];
    }
    // stage W = DT*Bm, [n][260]
    for (int i = tid; i < N_*D_; i += 512){
        int n = i >> 8, d = i & 255;
        sw[n*260 + d] = DTc * Bm[i];
    }
    __syncthreads();

    const int tl = tid >> 4, n = tid & 15;
    #pragma unroll
    for (int p = 0; p < 2; p++){
        int t = tl + 32*p;
        const float4* xr = (const float4*)(sx + t*260);
        const float4* wr = (const float4*)(sw + n*260);
        float acc = 0.f;
        #pragma unroll 4
        for (int q = 0; q < 64; q++){
            float4 xv = xr[q], wv = wr[q];
            acc = fmaf(xv.x, wv.x, acc);
            acc = fmaf(xv.y, wv.y, acc);
            acc = fmaf(xv.z, wv.z, acc);
            acc = fmaf(xv.w, wv.w, acc);
        }
        su[t*17 + n] = acc;
    }
    __syncthreads();

    // local scan: 16 chains (one per n), 64 steps each, h0 = 0
    if (tid < 16){
        float a = expf(-DTc*fabsf(A[tid]));
        float h = 0.f;
        #pragma unroll 8
        for (int t = 0; t < CHUNK; t++){
            h = fmaf(a, h, su[t*17 + tid]);
            su[t*17 + tid] = h;
        }
    }
    __syncthreads();

    float* Hg = g_H + (size_t)(b*S_ + chunk*CHUNK)*N_;
    for (int i = tid; i < CHUNK*N_; i += 512)
        Hg[i] = su[(i>>4)*17 + (i&15)];
}

// ---------------------------------------------------------------------------
// K2: carry recurrence across chunks. 256 threads = 16 b x 16 n.
// carry[c] = global h at index (64c - 1); carry[0] = 0.
// ---------------------------------------------------------------------------
__global__ void k2(const float* __restrict__ A){
    const int tid = threadIdx.x;           // 256
    const int b = tid >> 4, n = tid & 15;
    float a = expf(-DTc*fabsf(A[n]));
    float a2=a*a, a4=a2*a2, a8=a4*a4, a16=a8*a8, a32=a16*a16, a64=a32*a32;
    float carry = 0.f;
    #pragma unroll
    for (int c = 0; c < NCHUNK; c++){
        g_carry[b*(NCHUNK*N_) + c*N_ + n] = carry;
        float v = g_H[(size_t)(b*S_ + c*CHUNK + (CHUNK-1))*N_ + n];
        carry = fmaf(a64, carry, v);
    }
}

// ---------------------------------------------------------------------------
// K3: recombine carries, y = h @ Cm^T + x*Dv, clip, fused LayerNorm, store.
// 512 thr = 16 warps; warp-per-row, 4 rows per warp.
// ---------------------------------------------------------------------------
__global__ void __launch_bounds__(512,2) k3(const float* __restrict__ x,
                                            const float* __restrict__ A,
                                            const float* __restrict__ Cm,
                                            const float* __restrict__ Dv,
                                            const float* __restrict__ gamma,
                                            const float* __restrict__ beta,
                                            float* __restrict__ out){
    __shared__ float sC[D_*17];     // Cm[d][n] padded: bank = (17*lane + n)%32, conflict-free
    __shared__ float sh[CHUNK*17];  // h for the chunk
    __shared__ float sDv[D_], sg[D_], sb[D_];
    const int chunk = blockIdx.x, b = blockIdx.y;
    const int tid = threadIdx.x;

    for (int i = tid; i < D_*N_; i += 512)
        sC[(i>>4)*17 + (i&15)] = Cm[i];
    for (int i = tid; i < D_; i += 512){ sDv[i]=Dv[i]; sg[i]=gamma[i]; sb[i]=beta[i]; }
    const float* Hg = g_H + (size_t)(b*S_ + chunk*CHUNK)*N_;
    for (int i = tid; i < CHUNK*N_; i += 512)
        sh[(i>>4)*17 + (i&15)] = Hg[i];
    __syncthreads();

    // add a^{t+1} * carry_in to get global h
    if (tid < 16){
        float a = expf(-DTc*fabsf(A[tid]));
        float p = g_carry[b*(NCHUNK*N_) + chunk*N_ + tid];
        #pragma unroll 8
        for (int t = 0; t < CHUNK; t++){
            p *= a;
            sh[t*17 + tid] += p;
        }
    }
    __syncthreads();

    const int warp = tid >> 5, lane = tid & 31;
    for (int r = 0; r < 4; r++){
        int t = warp + 16*r;
        const float* xr = x + (size_t)(b*S_ + chunk*CHUNK + t)*D_;
        float y[8];
        #pragma unroll
        for (int j = 0; j < 8; j++){
            int d = lane + 32*j;
            y[j] = xr[d]*sDv[d];
        }
        const float* shr = sh + t*17;
        #pragma unroll
        for (int n = 0; n < 16; n++){
            float hv = shr[n];
            #pragma unroll
            for (int j = 0; j < 8; j++){
                int d = lane + 32*j;
                y[j] = fmaf(hv, sC[d*17 + n], y[j]);
            }
        }
        float s = 0.f, s2 = 0.f;
        #pragma unroll
        for (int j = 0; j < 8; j++){
            y[j] = fminf(fmaxf(y[j], -10.f), 10.f);
            s += y[j];
            s2 = fmaf(y[j], y[j], s2);
        }
        #pragma unroll
        for (int o = 16; o; o >>= 1){
            s  += __shfl_xor_sync(0xffffffffu, s,  o);
            s2 += __shfl_xor_sync(0xffffffffu, s2, o);
        }
        float mu   = s * (1.f/256.f);
        float var  = fmaf(s2, 1.f/256.f, -mu*mu);
        float rinv = rsqrtf(var + LN_EPS);
        float* og = out + (size_t)(b*S_ + chunk*CHUNK + t)*D_;
        #pragma unroll
        for (int j = 0; j < 8; j++){
            int d = lane + 32*j;
            og[d] = fmaf((y[j]-mu)*rinv, sg[d], sb[d]);
        }
    }
}

// ---------------------------------------------------------------------------
extern "C" void kernel_launch(void* const* d_in, const int* in_sizes, int n_in,
                              void* d_out, int out_size){
    const float* x     = (const float*)d_in[0];
    const float* A     = (const float*)d_in[1];
    const float* Bm    = (const float*)d_in[2];
    const float* Cm    = (const float*)d_in[3];
    const float* Dv    = (const float*)d_in[4];
    const float* gamma = (const float*)d_in[5];
    const float* beta  = (const float*)d_in[6];
    float* out = (float*)d_out;

    size_t smem1 = (size_t)(64*260 + 16*260 + 64*17) * sizeof(float); // 87552 B
    cudaFuncSetAttribute(k1, cudaFuncAttributeMaxDynamicSharedMemorySize, (int)smem1);

    dim3 grid(NCHUNK, B_);
    k1<<<grid, 512, smem1>>>(x, A, Bm);
    k2<<<1, 256>>>(A);
    k3<<<grid, 512>>>(x, A, Cm, Dv, gamma, beta, out);
}

// round 3
// speedup vs baseline: 2.3786x; 2.3786x over previous
#include <cuda_runtime.h>
#include <math.h>

#define DTc 1e-4f
#define LN_EPS 1e-5f
#define B_ 16
#define S_ 4096
#define D_ 256
#define N_ 16
#define CHUNK 64
#define NCHUNK (S_/CHUNK)   // 64
#define TPB1 256            // k1: 4 chunks (256 rows) per block

// scratch (no cudaMalloc allowed)
__device__ float g_H[B_*S_*N_];          // 4 MB: per-chunk local scans
__device__ float g_carry[B_*NCHUNK*N_];  // 64 KB

__device__ __forceinline__ void fma4(float4& acc, float s, const float4& v){
    acc.x = fmaf(s, v.x, acc.x);
    acc.y = fmaf(s, v.y, acc.y);
    acc.z = fmaf(s, v.z, acc.z);
    acc.w = fmaf(s, v.w, acc.w);
}

// ---------------------------------------------------------------------------
// K1: U = DT * x @ Bm^T for 256 rows (4 chunks), register-tiled 4t x 4n,
// then per-chunk local scans (h0 = 0). 256 threads.
// smem: sx[256][68] (one 64-col k-tile), swT[256][16], su[256][20]
// ---------------------------------------------------------------------------
__global__ void __launch_bounds__(TPB1,2) k1(const float* __restrict__ x,
                                             const float* __restrict__ A,
                                             const float* __restrict__ Bm){
    extern __shared__ float sm[];
    float* sx  = sm;                       // 256*68 = 17408
    float* swT = sm + 256*68;              // 256*16 = 4096   [k][n]
    float* su  = sm + 256*68 + 256*16;     // 256*20 = 5120   [t][n] pad 20
    const int blk = blockIdx.x, b = blockIdx.y;
    const int tid = threadIdx.x;
    const int nt = tid & 3, tt = tid >> 2;     // 4 n-tiles x 64 t-tiles

    // stage W transposed: swT[k][n] = DT * Bm[n][k]
    for (int i = tid; i < N_*D_; i += TPB1){
        int nn = i >> 8, k = i & 255;            // coalesced over k
        swT[k*16 + nn] = DTc * Bm[nn*D_ + k];
    }

    float4 acc[4];
    #pragma unroll
    for (int i = 0; i < 4; i++) acc[i] = make_float4(0.f,0.f,0.f,0.f);

    const float4* xg = (const float4*)(x + (size_t)(b*S_ + blk*256)*D_);
    const int q = tid & 15, t0s = tid >> 4;

    #pragma unroll
    for (int kt = 0; kt < 4; kt++){
        __syncthreads();
        // stage x k-tile: rows 0..255, cols kt*64..kt*64+63
        #pragma unroll
        for (int j = 0; j < 16; j++){
            int t = t0s + 16*j;
            *(float4*)(sx + t*68 + q*4) = xg[t*64 + kt*16 + q];
        }
        __syncthreads();

        const float4* xr0 = (const float4*)(sx + (tt*4+0)*68);
        const float4* xr1 = (const float4*)(sx + (tt*4+1)*68);
        const float4* xr2 = (const float4*)(sx + (tt*4+2)*68);
        const float4* xr3 = (const float4*)(sx + (tt*4+3)*68);
        const float* wb = swT + kt*64*16 + nt*4;

        #pragma unroll
        for (int k4 = 0; k4 < 16; k4++){
            float4 xa = xr0[k4], xb = xr1[k4], xc = xr2[k4], xd = xr3[k4];
            float4 w0 = *(const float4*)(wb + (k4*4+0)*16);
            float4 w1 = *(const float4*)(wb + (k4*4+1)*16);
            float4 w2 = *(const float4*)(wb + (k4*4+2)*16);
            float4 w3 = *(const float4*)(wb + (k4*4+3)*16);
            fma4(acc[0], xa.x, w0); fma4(acc[0], xa.y, w1); fma4(acc[0], xa.z, w2); fma4(acc[0], xa.w, w3);
            fma4(acc[1], xb.x, w0); fma4(acc[1], xb.y, w1); fma4(acc[1], xb.z, w2); fma4(acc[1], xb.w, w3);
            fma4(acc[2], xc.x, w0); fma4(acc[2], xc.y, w1); fma4(acc[2], xc.z, w2); fma4(acc[2], xc.w, w3);
            fma4(acc[3], xd.x, w0); fma4(acc[3], xd.y, w1); fma4(acc[3], xd.z, w2); fma4(acc[3], xd.w, w3);
        }
    }
    __syncthreads();
    #pragma unroll
    for (int i = 0; i < 4; i++)
        *(float4*)(su + (tt*4+i)*20 + nt*4) = acc[i];
    __syncthreads();

    // local scans: 64 chains (4 chunks x 16 n), h0 = 0
    if (tid < 64){
        int n = tid & 15, cc = tid >> 4;
        float a = expf(-DTc*fabsf(A[n]));
        float h = 0.f;
        float* p = su + cc*64*20 + n;
        #pragma unroll 8
        for (int t = 0; t < CHUNK; t++){
            h = fmaf(a, h, p[t*20]);
            p[t*20] = h;
        }
    }
    __syncthreads();

    float* Hg = g_H + (size_t)(b*S_ + blk*256)*N_;
    #pragma unroll
    for (int j = 0; j < 16; j++){
        int i = tid + j*TPB1;                 // 4096 elems
        Hg[i] = su[(i>>4)*20 + (i&15)];
    }
}

// ---------------------------------------------------------------------------
// K2: carry recurrence across chunks. 256 threads = 16 b x 16 n.
// ---------------------------------------------------------------------------
__global__ void k2(const float* __restrict__ A){
    const int tid = threadIdx.x;
    const int b = tid >> 4, n = tid & 15;
    float a = expf(-DTc*fabsf(A[n]));
    float a2=a*a, a4=a2*a2, a8=a4*a4, a16=a8*a8, a32=a16*a16, a64=a32*a32;
    float v[NCHUNK];
    #pragma unroll
    for (int c = 0; c < NCHUNK; c++)
        v[c] = g_H[(size_t)(b*S_ + c*CHUNK + (CHUNK-1))*N_ + n];
    float carry = 0.f;
    #pragma unroll
    for (int c = 0; c < NCHUNK; c++){
        g_carry[b*(NCHUNK*N_) + c*N_ + n] = carry;
        carry = fmaf(a64, carry, v[c]);
    }
}

// ---------------------------------------------------------------------------
// K3: recombine carries, y = h @ Cm^T + x*Dv, clip, fused LayerNorm, store.
// 512 thr = 16 warps; each warp owns 4 consecutive rows, processed together
// so every sC load is shared across 4 rows.
// ---------------------------------------------------------------------------
__global__ void __launch_bounds__(512,2) k3(const float* __restrict__ x,
                                            const float* __restrict__ A,
                                            const float* __restrict__ Cm,
                                            const float* __restrict__ Dv,
                                            const float* __restrict__ gamma,
                                            const float* __restrict__ beta,
                                            float* __restrict__ out){
    __shared__ float sC[D_*17];       // [d][n] pad 17: bank = (17d+n)%32 conflict-free
    __shared__ float sh[N_*68];       // [n][t] pad 68: broadcast float4 over t
    __shared__ float sDv[D_], sg[D_], sb[D_];
    const int chunk = blockIdx.x, b = blockIdx.y;
    const int tid = threadIdx.x;

    for (int i = tid; i < D_*N_; i += 512)
        sC[(i>>4)*17 + (i&15)] = Cm[i];
    for (int i = tid; i < D_; i += 512){ sDv[i]=Dv[i]; sg[i]=gamma[i]; sb[i]=beta[i]; }
    {
        const float* Hg = g_H + (size_t)(b*S_ + chunk*CHUNK)*N_;
        #pragma unroll
        for (int j = 0; j < 2; j++){
            int i = tid + j*512;           // 1024 elems
            int t = i >> 4, n = i & 15;
            sh[n*68 + t] = Hg[i];
        }
    }
    __syncthreads();

    // carry fixup: 64 threads, 16-step segments: h[t] += a^(t+1) * carry_in
    if (tid < 64){
        int n = tid & 15, seg = tid >> 4;
        float absA = fabsf(A[n]);
        float a = expf(-DTc*absA);
        float p = g_carry[b*(NCHUNK*N_) + chunk*N_ + n] * expf(-DTc*absA*(float)(seg*16));
        float* row = sh + n*68 + seg*16;
        #pragma unroll
        for (int tl = 0; tl < 16; tl++){
            p *= a;
            row[tl] += p;
        }
    }
    __syncthreads();

    const int warp = tid >> 5, lane = tid & 31;
    const int t0 = warp * 4;
    const float* xr = x + (size_t)(b*S_ + chunk*CHUNK + t0)*D_;

    float y[4][8];
    #pragma unroll
    for (int r = 0; r < 4; r++)
        #pragma unroll
        for (int j = 0; j < 8; j++){
            int d = lane + 32*j;
            y[r][j] = xr[r*D_ + d] * sDv[d];
        }

    #pragma unroll
    for (int n = 0; n < 16; n++){
        float4 h4 = *(const float4*)(sh + n*68 + t0);   // broadcast
        #pragma unroll
        for (int j = 0; j < 8; j++){
            int d = lane + 32*j;
            float c = sC[d*17 + n];
            y[0][j] = fmaf(h4.x, c, y[0][j]);
            y[1][j] = fmaf(h4.y, c, y[1][j]);
            y[2][j] = fmaf(h4.z, c, y[2][j]);
            y[3][j] = fmaf(h4.w, c, y[3][j]);
        }
    }

    float* og = out + (size_t)(b*S_ + chunk*CHUNK + t0)*D_;
    #pragma unroll
    for (int r = 0; r < 4; r++){
        float s = 0.f, s2 = 0.f;
        #pragma unroll
        for (int j = 0; j < 8; j++){
            float v = fminf(fmaxf(y[r][j], -10.f), 10.f);
            y[r][j] = v;
            s += v;
            s2 = fmaf(v, v, s2);
        }
        #pragma unroll
        for (int o = 16; o; o >>= 1){
            s  += __shfl_xor_sync(0xffffffffu, s,  o);
            s2 += __shfl_xor_sync(0xffffffffu, s2, o);
        }
        float mu   = s * (1.f/256.f);
        float var  = fmaf(s2, 1.f/256.f, -mu*mu);
        float rinv = rsqrtf(var + LN_EPS);
        #pragma unroll
        for (int j = 0; j < 8; j++){
            int d = lane + 32*j;
            og[r*D_ + d] = fmaf((y[r][j]-mu)*rinv, sg[d], sb[d]);
        }
    }
}

// ---------------------------------------------------------------------------
extern "C" void kernel_launch(void* const* d_in, const int* in_sizes, int n_in,
                              void* d_out, int out_size){
    const float* x     = (const float*)d_in[0];
    const float* A     = (const float*)d_in[1];
    const float* Bm    = (const float*)d_in[2];
    const float* Cm    = (const float*)d_in[3];
    const float* Dv    = (const float*)d_in[4];
    const float* gamma = (const float*)d_in[5];
    const float* beta  = (const float*)d_in[6];
    float* out = (float*)d_out;

    size_t smem1 = (size_t)(256*68 + 256*16 + 256*20) * sizeof(float); // 106496 B
    cudaFuncSetAttribute(k1, cudaFuncAttributeMaxDynamicSharedMemorySize, (int)smem1);

    dim3 grid1(NCHUNK/4, B_);   // 16 x 16
    dim3 grid3(NCHUNK, B_);     // 64 x 16
    k1<<<grid1, TPB1, smem1>>>(x, A, Bm);
    k2<<<1, 256>>>(A);
    k3<<<grid3, 512>>>(x, A, Cm, Dv, gamma, beta, out);
}